// round 4
// baseline (speedup 1.0000x reference)
#include <cuda_runtime.h>
#include <math_constants.h>

#define BB   32
#define TT   2048
#define SINDIM 1024
#define HINDIM 1024
#define KDIM 512
#define VDIM 512
#define NBLK 16            // main-kernel chunks per batch
#define WPB  8             // warps per block
#define PW   (NBLK*WPB)    // t-stride (128)

// ---- scratch (device globals; no allocations allowed) ----
__device__ float g_query[BB*KDIM];
__device__ float g_qh[BB*HINDIM];
__device__ float g_e[BB*TT];
__device__ float g_pm[BB*NBLK];
__device__ float g_pz[BB*NBLK];
__device__ float g_pacc[BB*NBLK*HINDIM];
__device__ float g_ctxh[BB*HINDIM];
__device__ int   g_cnt[BB];          // zero-init; merging block resets -> replay-safe

__device__ __forceinline__ float warp_sum(float v) {
#pragma unroll
    for (int o = 16; o > 0; o >>= 1) v += __shfl_xor_sync(0xffffffffu, v, o);
    return v;
}
__device__ __forceinline__ float warp_max(float v) {
#pragma unroll
    for (int o = 16; o > 0; o >>= 1) v = fmaxf(v, __shfl_xor_sync(0xffffffffu, v, o));
    return v;
}

// query[b,k] = Ws[k,:]·dec[b,:] + bs[k].  One warp computes k for 4 batches.
__global__ void k_query(const float* __restrict__ dec, const float* __restrict__ Ws,
                        const float* __restrict__ bs) {
    int gw   = blockIdx.x * WPB + (threadIdx.x >> 5);
    int lane = threadIdx.x & 31;
    int k  = gw % KDIM;
    int b0 = (gw / KDIM) * 4;
    const float4* w4 = (const float4*)(Ws + (size_t)k * SINDIM);
    float4 w[8];
#pragma unroll
    for (int j = 0; j < 8; j++) w[j] = w4[lane + 32*j];
    float bias = bs[k];
#pragma unroll
    for (int bb = 0; bb < 4; bb++) {
        const float4* s4 = (const float4*)(dec + (size_t)(b0+bb) * SINDIM);
        float a = 0.f;
#pragma unroll
        for (int j = 0; j < 8; j++) {
            float4 s = s4[lane + 32*j];
            a += w[j].x*s.x + w[j].y*s.y + w[j].z*s.z + w[j].w*s.w;
        }
        a = warp_sum(a);
        if (lane == 0) g_query[(b0+bb)*KDIM + k] = a + bias;
    }
}

// qh[b,h] = sum_k Wh[k,h]*query[b,k].  Single pass, no partials.
// grid (HINDIM/128, BB/4), 256 threads.
__global__ void __launch_bounds__(256) k_qh(const float* __restrict__ Wh) {
    __shared__ float sq[4][KDIM];
    const int tid  = threadIdx.x;
    const int h    = blockIdx.x * 128 + (tid & 127);
    const int bsel = tid >> 7;                  // 0 or 1
    const int b0   = blockIdx.y * 4;
    for (int i = tid; i < 4*KDIM; i += 256)
        sq[i >> 9][i & (KDIM-1)] = g_query[(b0 + (i >> 9))*KDIM + (i & (KDIM-1))];
    __syncthreads();
    const float* sq0 = sq[2*bsel], *sq1 = sq[2*bsel+1];
    float a0 = 0.f, a1 = 0.f;
#pragma unroll 4
    for (int k = 0; k < KDIM; k++) {
        float wh = Wh[(size_t)k * HINDIM + h];
        a0 += wh * sq0[k];
        a1 += wh * sq1[k];
    }
    g_qh[(b0 + 2*bsel    )*HINDIM + h] = a0;
    g_qh[(b0 + 2*bsel + 1)*HINDIM + h] = a1;
}

// MAIN: streaming masked online-softmax pass; last block per batch merges,
// writes attn and ctxh.  grid = NBLK*BB (b = blockIdx.x & 31), 256 threads.
__global__ void __launch_bounds__(256) k_main(const float* __restrict__ lo,
                                              const int* __restrict__ lens,
                                              float* __restrict__ out) {
    __shared__ float s_m[WPB], s_zs[WPB];
    __shared__ float s_acc[WPB][HINDIM];
    __shared__ float s_f[NBLK];
    __shared__ float s_bm, s_binvZ;
    __shared__ int   s_last;

    const int b      = blockIdx.x & (BB-1);
    const int chunk  = blockIdx.x >> 5;
    const int warpId = threadIdx.x >> 5;
    const int lane   = threadIdx.x & 31;
    const int ws     = chunk * WPB + warpId;
    const int len    = (b == 0) ? TT : lens[b];   // ref never masks sample 0

    const float4* qh4 = (const float4*)(g_qh + (size_t)b * HINDIM);
    float4 q[8];
#pragma unroll
    for (int j = 0; j < 8; j++) q[j] = qh4[lane + 32*j];

    float4 acc[8];
#pragma unroll
    for (int j = 0; j < 8; j++) acc[j] = make_float4(0.f,0.f,0.f,0.f);
    float m = -CUDART_INF_F, Z = 0.f;

    const float4* lob = (const float4*)(lo + (size_t)b * TT * HINDIM);
    for (int t = ws; t < len; t += PW) {
        const float4* h4 = lob + (size_t)t * (HINDIM/4);
        float4 hv[8];
#pragma unroll
        for (int j = 0; j < 8; j++) hv[j] = h4[lane + 32*j];
        float e = 0.f;
#pragma unroll
        for (int j = 0; j < 8; j++)
            e += hv[j].x*q[j].x + hv[j].y*q[j].y + hv[j].z*q[j].z + hv[j].w*q[j].w;
        e = warp_sum(e);                       // warp-uniform
        if (lane == 0) g_e[b*TT + t] = e;
        if (e > m) {                           // uniform branch
            float f = (m > -CUDART_INF_F) ? __expf(m - e) : 0.f;
            Z = Z * f + 1.f;
#pragma unroll
            for (int j = 0; j < 8; j++) {
                acc[j].x = acc[j].x * f + hv[j].x;
                acc[j].y = acc[j].y * f + hv[j].y;
                acc[j].z = acc[j].z * f + hv[j].z;
                acc[j].w = acc[j].w * f + hv[j].w;
            }
            m = e;
        } else {
            float w = __expf(e - m);
            Z += w;
#pragma unroll
            for (int j = 0; j < 8; j++) {
                acc[j].x += w * hv[j].x;
                acc[j].y += w * hv[j].y;
                acc[j].z += w * hv[j].z;
                acc[j].w += w * hv[j].w;
            }
        }
    }

    // ---- in-block merge of 8 warp partials ----
    if (lane == 0) s_m[warpId] = m;
    __syncthreads();
    float mb = s_m[0];
#pragma unroll
    for (int w = 1; w < WPB; w++) mb = fmaxf(mb, s_m[w]);
    float f = (m > -CUDART_INF_F) ? __expf(m - mb) : 0.f;
    if (lane == 0) s_zs[warpId] = Z * f;
    float4* sa = (float4*)(&s_acc[warpId][0]);
#pragma unroll
    for (int j = 0; j < 8; j++) {
        float4 v = acc[j];
        v.x *= f; v.y *= f; v.z *= f; v.w *= f;
        sa[lane + 32*j] = v;
    }
    __syncthreads();
    const int pid = b * NBLK + chunk;
    for (int h = threadIdx.x; h < HINDIM; h += 256) {
        float s = 0.f;
#pragma unroll
        for (int w = 0; w < WPB; w++) s += s_acc[w][h];
        g_pacc[(size_t)pid * HINDIM + h] = s;
    }
    if (threadIdx.x == 0) {
        float zb = 0.f;
#pragma unroll
        for (int w = 0; w < WPB; w++) zb += s_zs[w];
        g_pm[pid] = mb; g_pz[pid] = zb;
    }
    __syncthreads();

    // ---- last block of this batch performs the cross-block merge ----
    if (threadIdx.x == 0) {
        __threadfence();                       // release partials + g_e
        int r = atomicAdd(&g_cnt[b], 1);
        s_last = (r == NBLK - 1);
        if (s_last) g_cnt[b] = 0;              // self-reset for next replay
    }
    __syncthreads();
    if (!s_last) return;
    __threadfence();                           // acquire: see all partials

    // FULL warp participates in the shuffles (lanes >= NBLK contribute identity)
    if (threadIdx.x < 32) {
        int  j    = threadIdx.x;
        bool live = (j < NBLK);
        float pm = live ? g_pm[b*NBLK + j] : -CUDART_INF_F;
        float mm = warp_max(pm);
        float fj = (pm > -CUDART_INF_F) ? __expf(pm - mm) : 0.f;
        float zc = live ? g_pz[b*NBLK + j] * fj : 0.f;
        float z  = warp_sum(zc);
        if (live) s_f[j] = fj;
        if (j == 0) { s_bm = mm; s_binvZ = 1.f / fmaxf(z, 1e-12f); }
    }
    __syncthreads();
    const float bm = s_bm, invZ = s_binvZ;

    for (int h = threadIdx.x; h < HINDIM; h += 256) {
        float s = 0.f;
#pragma unroll
        for (int j = 0; j < NBLK; j++)
            s += g_pacc[(size_t)(b*NBLK + j)*HINDIM + h] * s_f[j];
        g_ctxh[b*HINDIM + h] = s * invZ;
    }
    float* oat = out + BB*VDIM + (size_t)b*TT;
    for (int t = threadIdx.x; t < TT; t += 256)
        oat[t] = (t < len) ? __expf(g_e[b*TT + t] - bm) * invZ : 0.f;
}

// context[b,v] = Wv[v,:]·ctxh[b,:] + bv[v].
// 64 blocks × 8 warps: warp owns one v for ALL 32 batches (Wv row loaded once).
__global__ void __launch_bounds__(256) k_context(const float* __restrict__ Wv,
                                                 const float* __restrict__ bv,
                                                 float* __restrict__ out) {
    int v    = blockIdx.x * WPB + (threadIdx.x >> 5);
    int lane = threadIdx.x & 31;
    const float4* w4 = (const float4*)(Wv + (size_t)v * HINDIM);
    float4 w[8];
#pragma unroll
    for (int j = 0; j < 8; j++) w[j] = w4[lane + 32*j];
    float bias = bv[v];
#pragma unroll 4
    for (int b = 0; b < BB; b++) {
        const float4* c4 = (const float4*)(g_ctxh + (size_t)b * HINDIM);
        float a = 0.f;
#pragma unroll
        for (int j = 0; j < 8; j++) {
            float4 c = c4[lane + 32*j];
            a += w[j].x*c.x + w[j].y*c.y + w[j].z*c.z + w[j].w*c.w;
        }
        a = warp_sum(a);
        if (lane == 0) out[b*VDIM + v] = a + bias;
    }
}

extern "C" void kernel_launch(void* const* d_in, const int* in_sizes, int n_in,
                              void* d_out, int out_size) {
    const float* dec = (const float*)d_in[0];
    const float* lo  = (const float*)d_in[1];
    const int*   len = (const int*)  d_in[2];
    const float* Ws  = (const float*)d_in[3];
    const float* bs  = (const float*)d_in[4];
    const float* Wh  = (const float*)d_in[5];
    const float* bh  = (const float*)d_in[6];  // unused: cancels in softmax
    const float* Wv  = (const float*)d_in[7];
    const float* bv  = (const float*)d_in[8];
    float* out = (float*)d_out;
    (void)bh;

    k_query  <<<KDIM * (BB/4) / WPB, 256>>>(dec, Ws, bs);     // 512 blocks
    k_qh     <<<dim3(HINDIM/128, BB/4), 256>>>(Wh);           // 64 blocks
    k_main   <<<NBLK * BB, 256>>>(lo, len, out);              // 512 blocks
    k_context<<<VDIM / WPB, 256>>>(Wv, bv, out);              // 64 blocks
}

// round 5
// speedup vs baseline: 1.1912x; 1.1912x over previous
#include <cuda_runtime.h>
#include <math_constants.h>

#define BB   32
#define TT   2048
#define SINDIM 1024
#define HINDIM 1024
#define KDIM 512
#define VDIM 512
#define NBLK 16            // main-kernel chunks per batch
#define WPB  8             // warps per block
#define PW   (NBLK*WPB)    // t-stride (128)
#define KSPLIT 4
#define KCH  (KDIM/KSPLIT) // 128

// ---- scratch (device globals; no allocations allowed) ----
__device__ float g_query[BB*KDIM];
__device__ float g_qhp[KSPLIT*BB*HINDIM];
__device__ float g_e[BB*TT];
__device__ float g_pm[BB*NBLK];
__device__ float g_pz[BB*NBLK];
__device__ float g_pacc[BB*NBLK*HINDIM];
__device__ float g_ctxh[BB*HINDIM];
__device__ int   g_cnt[BB];          // zero-init; merging block resets -> replay-safe

__device__ __forceinline__ float warp_sum(float v) {
#pragma unroll
    for (int o = 16; o > 0; o >>= 1) v += __shfl_xor_sync(0xffffffffu, v, o);
    return v;
}
__device__ __forceinline__ float warp_max(float v) {
#pragma unroll
    for (int o = 16; o > 0; o >>= 1) v = fmaxf(v, __shfl_xor_sync(0xffffffffu, v, o));
    return v;
}

// query[b,k] = Ws[k,:]·dec[b,:] + bs[k].  One warp computes k for 4 batches.
__global__ void k_query(const float* __restrict__ dec, const float* __restrict__ Ws,
                        const float* __restrict__ bs) {
    int gw   = blockIdx.x * WPB + (threadIdx.x >> 5);
    int lane = threadIdx.x & 31;
    int k  = gw % KDIM;
    int b0 = (gw / KDIM) * 4;
    const float4* w4 = (const float4*)(Ws + (size_t)k * SINDIM);
    float4 w[8];
#pragma unroll
    for (int j = 0; j < 8; j++) w[j] = w4[lane + 32*j];
    float bias = bs[k];
#pragma unroll
    for (int bb = 0; bb < 4; bb++) {
        const float4* s4 = (const float4*)(dec + (size_t)(b0+bb) * SINDIM);
        float a = 0.f;
#pragma unroll
        for (int j = 0; j < 8; j++) {
            float4 s = s4[lane + 32*j];
            a += w[j].x*s.x + w[j].y*s.y + w[j].z*s.z + w[j].w*s.w;
        }
        a = warp_sum(a);
        if (lane == 0) g_query[(b0+bb)*KDIM + k] = a + bias;
    }
}

// qh partials: qhp[s][b][h] = sum_{k in chunk s} Wh[k,h]*query[b,k]
// grid (HINDIM/256, KSPLIT), 256 threads.  acc[32] in regs -> 32 indep FMA/load.
__global__ void __launch_bounds__(256) k_qhp(const float* __restrict__ Wh) {
    __shared__ float sq[BB][KCH];          // 16 KB
    const int tid = threadIdx.x;
    const int h   = blockIdx.x * 256 + tid;
    const int k0  = blockIdx.y * KCH;
    for (int i = tid; i < BB*KCH; i += 256)
        sq[i >> 7][i & (KCH-1)] = g_query[(i >> 7)*KDIM + k0 + (i & (KCH-1))];
    __syncthreads();
    float acc[BB];
#pragma unroll
    for (int b = 0; b < BB; b++) acc[b] = 0.f;
#pragma unroll 2
    for (int kk = 0; kk < KCH; kk++) {
        float wh = Wh[(size_t)(k0+kk) * HINDIM + h];
#pragma unroll
        for (int b = 0; b < BB; b++) acc[b] += wh * sq[b][kk];
    }
#pragma unroll
    for (int b = 0; b < BB; b++)
        g_qhp[((size_t)blockIdx.y*BB + b)*HINDIM + h] = acc[b];
}

// MAIN: streaming masked online-softmax pass; last block per batch merges,
// writes attn and ctxh.  grid = NBLK*BB (b = blockIdx.x & 31), 256 threads.
__global__ void __launch_bounds__(256) k_main(const float* __restrict__ lo,
                                              const int* __restrict__ lens,
                                              float* __restrict__ out) {
    __shared__ float s_m[WPB], s_zs[WPB];
    __shared__ float s_acc[WPB][HINDIM];
    __shared__ float s_f[NBLK];
    __shared__ float s_bm, s_binvZ;
    __shared__ int   s_last;

    const int b      = blockIdx.x & (BB-1);
    const int chunk  = blockIdx.x >> 5;
    const int warpId = threadIdx.x >> 5;
    const int lane   = threadIdx.x & 31;
    const int ws     = chunk * WPB + warpId;
    const int len    = (b == 0) ? TT : lens[b];   // ref never masks sample 0

    // merge the KSPLIT=4 qh partials in-register (16 KB L2 reads per block)
    float4 q[8];
#pragma unroll
    for (int j = 0; j < 8; j++) q[j] = make_float4(0.f,0.f,0.f,0.f);
#pragma unroll
    for (int s = 0; s < KSPLIT; s++) {
        const float4* p4 = (const float4*)(g_qhp + ((size_t)s*BB + b)*HINDIM);
#pragma unroll
        for (int j = 0; j < 8; j++) {
            float4 v = p4[lane + 32*j];
            q[j].x += v.x; q[j].y += v.y; q[j].z += v.z; q[j].w += v.w;
        }
    }

    float4 acc[8];
#pragma unroll
    for (int j = 0; j < 8; j++) acc[j] = make_float4(0.f,0.f,0.f,0.f);
    float m = -CUDART_INF_F, Z = 0.f;

    const float4* lob = (const float4*)(lo + (size_t)b * TT * HINDIM);
    for (int t = ws; t < len; t += PW) {
        const float4* h4 = lob + (size_t)t * (HINDIM/4);
        float4 hv[8];
#pragma unroll
        for (int j = 0; j < 8; j++) hv[j] = h4[lane + 32*j];
        float e = 0.f;
#pragma unroll
        for (int j = 0; j < 8; j++)
            e += hv[j].x*q[j].x + hv[j].y*q[j].y + hv[j].z*q[j].z + hv[j].w*q[j].w;
        e = warp_sum(e);                       // warp-uniform
        if (lane == 0) g_e[b*TT + t] = e;
        if (e > m) {                           // uniform branch
            float f = (m > -CUDART_INF_F) ? __expf(m - e) : 0.f;
            Z = Z * f + 1.f;
#pragma unroll
            for (int j = 0; j < 8; j++) {
                acc[j].x = acc[j].x * f + hv[j].x;
                acc[j].y = acc[j].y * f + hv[j].y;
                acc[j].z = acc[j].z * f + hv[j].z;
                acc[j].w = acc[j].w * f + hv[j].w;
            }
            m = e;
        } else {
            float w = __expf(e - m);
            Z += w;
#pragma unroll
            for (int j = 0; j < 8; j++) {
                acc[j].x += w * hv[j].x;
                acc[j].y += w * hv[j].y;
                acc[j].z += w * hv[j].z;
                acc[j].w += w * hv[j].w;
            }
        }
    }

    // ---- in-block merge of 8 warp partials ----
    if (lane == 0) s_m[warpId] = m;
    __syncthreads();
    float mb = s_m[0];
#pragma unroll
    for (int w = 1; w < WPB; w++) mb = fmaxf(mb, s_m[w]);
    float f = (m > -CUDART_INF_F) ? __expf(m - mb) : 0.f;
    if (lane == 0) s_zs[warpId] = Z * f;
    float4* sa = (float4*)(&s_acc[warpId][0]);
#pragma unroll
    for (int j = 0; j < 8; j++) {
        float4 v = acc[j];
        v.x *= f; v.y *= f; v.z *= f; v.w *= f;
        sa[lane + 32*j] = v;
    }
    __syncthreads();
    const int pid = b * NBLK + chunk;
    for (int h = threadIdx.x; h < HINDIM; h += 256) {
        float s = 0.f;
#pragma unroll
        for (int w = 0; w < WPB; w++) s += s_acc[w][h];
        g_pacc[(size_t)pid * HINDIM + h] = s;
    }
    if (threadIdx.x == 0) {
        float zb = 0.f;
#pragma unroll
        for (int w = 0; w < WPB; w++) zb += s_zs[w];
        g_pm[pid] = mb; g_pz[pid] = zb;
    }
    __syncthreads();

    // ---- last block of this batch performs the cross-block merge ----
    if (threadIdx.x == 0) {
        __threadfence();                       // release partials + g_e
        int r = atomicAdd(&g_cnt[b], 1);
        s_last = (r == NBLK - 1);
        if (s_last) g_cnt[b] = 0;              // self-reset for next replay
    }
    __syncthreads();
    if (!s_last) return;
    __threadfence();                           // acquire: see all partials

    // FULL warp participates in the shuffles (lanes >= NBLK contribute identity)
    if (threadIdx.x < 32) {
        int  j    = threadIdx.x;
        bool live = (j < NBLK);
        float pm = live ? g_pm[b*NBLK + j] : -CUDART_INF_F;
        float mm = warp_max(pm);
        float fj = (pm > -CUDART_INF_F) ? __expf(pm - mm) : 0.f;
        float zc = live ? g_pz[b*NBLK + j] * fj : 0.f;
        float z  = warp_sum(zc);
        if (live) s_f[j] = fj;
        if (j == 0) { s_bm = mm; s_binvZ = 1.f / fmaxf(z, 1e-12f); }
    }
    __syncthreads();
    const float bm = s_bm, invZ = s_binvZ;

    for (int h = threadIdx.x; h < HINDIM; h += 256) {
        float s = 0.f;
#pragma unroll
        for (int j = 0; j < NBLK; j++)
            s += g_pacc[(size_t)(b*NBLK + j)*HINDIM + h] * s_f[j];
        g_ctxh[b*HINDIM + h] = s * invZ;
    }
    float* oat = out + BB*VDIM + (size_t)b*TT;
    for (int t = threadIdx.x; t < TT; t += 256)
        oat[t] = (t < len) ? __expf(g_e[b*TT + t] - bm) * invZ : 0.f;
}

// context[b,v] = Wv[v,:]·ctxh[b,:] + bv[v].  Warp = one v x 4 batches (R2 shape).
__global__ void k_context(const float* __restrict__ Wv, const float* __restrict__ bv,
                          float* __restrict__ out) {
    int gw   = blockIdx.x * WPB + (threadIdx.x >> 5);
    int lane = threadIdx.x & 31;
    int v  = gw % VDIM;
    int b0 = (gw / VDIM) * 4;
    const float4* w4 = (const float4*)(Wv + (size_t)v * HINDIM);
    float4 w[8];
#pragma unroll
    for (int j = 0; j < 8; j++) w[j] = w4[lane + 32*j];
    float bias = bv[v];
#pragma unroll
    for (int bb = 0; bb < 4; bb++) {
        const float4* c4 = (const float4*)(g_ctxh + (size_t)(b0+bb) * HINDIM);
        float a = 0.f;
#pragma unroll
        for (int j = 0; j < 8; j++) {
            float4 c = c4[lane + 32*j];
            a += w[j].x*c.x + w[j].y*c.y + w[j].z*c.z + w[j].w*c.w;
        }
        a = warp_sum(a);
        if (lane == 0) out[(b0+bb)*VDIM + v] = a + bias;
    }
}

extern "C" void kernel_launch(void* const* d_in, const int* in_sizes, int n_in,
                              void* d_out, int out_size) {
    const float* dec = (const float*)d_in[0];
    const float* lo  = (const float*)d_in[1];
    const int*   len = (const int*)  d_in[2];
    const float* Ws  = (const float*)d_in[3];
    const float* bs  = (const float*)d_in[4];
    const float* Wh  = (const float*)d_in[5];
    const float* bh  = (const float*)d_in[6];  // unused: cancels in softmax
    const float* Wv  = (const float*)d_in[7];
    const float* bv  = (const float*)d_in[8];
    float* out = (float*)d_out;
    (void)bh;

    k_query  <<<KDIM * (BB/4) / WPB, 256>>>(dec, Ws, bs);     // 512 blocks
    k_qhp    <<<dim3(HINDIM/256, KSPLIT), 256>>>(Wh);         // 16 blocks
    k_main   <<<NBLK * BB, 256>>>(lo, len, out);              // 512 blocks
    k_context<<<VDIM * (BB/4) / WPB, 256>>>(Wv, bv, out);     // 512 blocks
}

// round 7
// speedup vs baseline: 1.2133x; 1.0186x over previous
#include <cuda_runtime.h>
#include <math_constants.h>

#define BB   32
#define TT   2048
#define SINDIM 1024
#define HINDIM 1024
#define KDIM 512
#define VDIM 512
#define NBLK 16            // main-kernel chunks per batch
#define WPB  8             // warps per block
#define PW   (NBLK*WPB)    // t-stride (128)
#define KSPLIT 4
#define KCH  (KDIM/KSPLIT) // 128

// ---- scratch (device globals; no allocations allowed) ----
__device__ float g_query[BB*KDIM];
__device__ float g_qhp[KSPLIT*BB*HINDIM];
__device__ float g_e[BB*TT];
__device__ float g_pm[BB*NBLK];
__device__ float g_pz[BB*NBLK];
__device__ float g_pacc[BB*NBLK*HINDIM];
__device__ float g_ctxh[BB*HINDIM];

__device__ __forceinline__ float warp_sum(float v) {
#pragma unroll
    for (int o = 16; o > 0; o >>= 1) v += __shfl_xor_sync(0xffffffffu, v, o);
    return v;
}

// query[b,k] = Ws[k,:]·dec[b,:] + bs[k].  One warp computes k for 4 batches.
__global__ void k_query(const float* __restrict__ dec, const float* __restrict__ Ws,
                        const float* __restrict__ bs) {
    int gw   = blockIdx.x * WPB + (threadIdx.x >> 5);
    int lane = threadIdx.x & 31;
    int k  = gw % KDIM;
    int b0 = (gw / KDIM) * 4;
    const float4* w4 = (const float4*)(Ws + (size_t)k * SINDIM);
    float4 w[8];
#pragma unroll
    for (int j = 0; j < 8; j++) w[j] = w4[lane + 32*j];
    float bias = bs[k];
#pragma unroll
    for (int bb = 0; bb < 4; bb++) {
        const float4* s4 = (const float4*)(dec + (size_t)(b0+bb) * SINDIM);
        float a = 0.f;
#pragma unroll
        for (int j = 0; j < 8; j++) {
            float4 s = s4[lane + 32*j];
            a += w[j].x*s.x + w[j].y*s.y + w[j].z*s.z + w[j].w*s.w;
        }
        a = warp_sum(a);
        if (lane == 0) g_query[(b0+bb)*KDIM + k] = a + bias;
    }
}

// qh partials: qhp[s][b][h] = sum_{k in chunk s} Wh[k,h]*query[b,k]
// grid (HINDIM/256, KSPLIT), 256 threads.  acc[32] in regs -> 32 indep FMA/load.
__global__ void __launch_bounds__(256) k_qhp(const float* __restrict__ Wh) {
    __shared__ float sq[BB][KCH];          // 16 KB
    const int tid = threadIdx.x;
    const int h   = blockIdx.x * 256 + tid;
    const int k0  = blockIdx.y * KCH;
    for (int i = tid; i < BB*KCH; i += 256)
        sq[i >> 7][i & (KCH-1)] = g_query[(i >> 7)*KDIM + k0 + (i & (KCH-1))];
    __syncthreads();
    float acc[BB];
#pragma unroll
    for (int b = 0; b < BB; b++) acc[b] = 0.f;
#pragma unroll 2
    for (int kk = 0; kk < KCH; kk++) {
        float wh = Wh[(size_t)(k0+kk) * HINDIM + h];
#pragma unroll
        for (int b = 0; b < BB; b++) acc[b] += wh * sq[b][kk];
    }
#pragma unroll
    for (int b = 0; b < BB; b++)
        g_qhp[((size_t)blockIdx.y*BB + b)*HINDIM + h] = acc[b];
}

// MAIN: streaming masked online-softmax pass (no tail fusion).
// grid = NBLK*BB (b = blockIdx.x & 31), 256 threads.
__global__ void __launch_bounds__(256) k_main(const float* __restrict__ lo,
                                              const int* __restrict__ lens) {
    __shared__ float s_q[HINDIM];          // 4 KB: merged qh for this batch
    __shared__ float s_m[WPB], s_zs[WPB];
    __shared__ float s_acc[WPB][HINDIM];   // 32 KB

    const int b      = blockIdx.x & (BB-1);
    const int chunk  = blockIdx.x >> 5;
    const int warpId = threadIdx.x >> 5;
    const int lane   = threadIdx.x & 31;
    const int ws     = chunk * WPB + warpId;
    const int len    = (b == 0) ? TT : lens[b];   // ref never masks sample 0

    // cooperative prologue: merge KSPLIT partials into s_q (16 KB L2 reads)
    {
        int i = threadIdx.x;                      // one float4 per thread
        float4 v = make_float4(0.f,0.f,0.f,0.f);
#pragma unroll
        for (int s = 0; s < KSPLIT; s++) {
            float4 p = ((const float4*)(g_qhp + ((size_t)s*BB + b)*HINDIM))[i];
            v.x += p.x; v.y += p.y; v.z += p.z; v.w += p.w;
        }
        ((float4*)s_q)[i] = v;
    }
    __syncthreads();

    float4 acc[8];
#pragma unroll
    for (int j = 0; j < 8; j++) acc[j] = make_float4(0.f,0.f,0.f,0.f);
    float m = -CUDART_INF_F, Z = 0.f;

    const float4* lob = (const float4*)(lo + (size_t)b * TT * HINDIM);
    const float4* sq4 = (const float4*)s_q;

    float4 hv[8];
    if (ws < len) {
        const float4* h4 = lob + (size_t)ws * (HINDIM/4);
#pragma unroll
        for (int j = 0; j < 8; j++) hv[j] = h4[lane + 32*j];
    }
    for (int t = ws; t < len; t += PW) {
        // prefetch next row before the serial reduce chain
        float4 nx[8];
        const int tn = t + PW;
        if (tn < len) {
            const float4* h4 = lob + (size_t)tn * (HINDIM/4);
#pragma unroll
            for (int j = 0; j < 8; j++) nx[j] = h4[lane + 32*j];
        }
        float e = 0.f;
#pragma unroll
        for (int j = 0; j < 8; j++) {
            float4 qv = sq4[lane + 32*j];
            e += hv[j].x*qv.x + hv[j].y*qv.y + hv[j].z*qv.z + hv[j].w*qv.w;
        }
        e = warp_sum(e);                       // warp-uniform
        if (lane == 0) g_e[b*TT + t] = e;
        if (e > m) {                           // uniform branch
            float f = (m > -CUDART_INF_F) ? __expf(m - e) : 0.f;
            Z = Z * f + 1.f;
#pragma unroll
            for (int j = 0; j < 8; j++) {
                acc[j].x = acc[j].x * f + hv[j].x;
                acc[j].y = acc[j].y * f + hv[j].y;
                acc[j].z = acc[j].z * f + hv[j].z;
                acc[j].w = acc[j].w * f + hv[j].w;
            }
            m = e;
        } else {
            float w = __expf(e - m);
            Z += w;
#pragma unroll
            for (int j = 0; j < 8; j++) {
                acc[j].x += w * hv[j].x;
                acc[j].y += w * hv[j].y;
                acc[j].z += w * hv[j].z;
                acc[j].w += w * hv[j].w;
            }
        }
#pragma unroll
        for (int j = 0; j < 8; j++) hv[j] = nx[j];
    }

    // ---- in-block merge of 8 warp partials ----
    if (lane == 0) s_m[warpId] = m;
    __syncthreads();
    float mb = s_m[0];
#pragma unroll
    for (int w = 1; w < WPB; w++) mb = fmaxf(mb, s_m[w]);
    float f = (m > -CUDART_INF_F) ? __expf(m - mb) : 0.f;
    if (lane == 0) s_zs[warpId] = Z * f;
    float4* sa = (float4*)(&s_acc[warpId][0]);
#pragma unroll
    for (int j = 0; j < 8; j++) {
        float4 v = acc[j];
        v.x *= f; v.y *= f; v.z *= f; v.w *= f;
        sa[lane + 32*j] = v;
    }
    __syncthreads();
    const int pid = b * NBLK + chunk;
    for (int h = threadIdx.x; h < HINDIM; h += 256) {
        float s = 0.f;
#pragma unroll
        for (int w = 0; w < WPB; w++) s += s_acc[w][h];
        g_pacc[(size_t)pid * HINDIM + h] = s;
    }
    if (threadIdx.x == 0) {
        float zb = 0.f;
#pragma unroll
        for (int w = 0; w < WPB; w++) zb += s_zs[w];
        g_pm[pid] = mb; g_pz[pid] = zb;
    }
}

// cross-block LSE merge per batch; emits attn and ctxh.
__global__ void k_bmerge(const int* __restrict__ lens, float* __restrict__ out) {
    __shared__ float sf[NBLK];
    __shared__ float red[256];
    const int b = blockIdx.x, tid = threadIdx.x;
    float m = -CUDART_INF_F;
    if (tid < NBLK) m = g_pm[b*NBLK + tid];
    red[tid] = m; __syncthreads();
#pragma unroll
    for (int s = 128; s > 0; s >>= 1) {
        if (tid < s) red[tid] = fmaxf(red[tid], red[tid+s]);
        __syncthreads();
    }
    m = red[0];
    __syncthreads();
    float zc = 0.f;
    if (tid < NBLK) {
        float pm = g_pm[b*NBLK + tid];
        float fj = (pm > -CUDART_INF_F) ? __expf(pm - m) : 0.f;
        sf[tid] = fj;
        zc = g_pz[b*NBLK + tid] * fj;
    }
    red[tid] = zc; __syncthreads();
#pragma unroll
    for (int s = 128; s > 0; s >>= 1) {
        if (tid < s) red[tid] += red[tid+s];
        __syncthreads();
    }
    float invZ = 1.f / fmaxf(red[0], 1e-12f);

    for (int h = tid; h < HINDIM; h += 256) {
        float s = 0.f;
#pragma unroll
        for (int j = 0; j < NBLK; j++)
            s += g_pacc[(size_t)(b*NBLK + j)*HINDIM + h] * sf[j];
        g_ctxh[b*HINDIM + h] = s * invZ;
    }
    const int len = (b == 0) ? TT : lens[b];
    float* oat = out + BB*VDIM + (size_t)b*TT;
    for (int t = tid; t < TT; t += 256)
        oat[t] = (t < len) ? __expf(g_e[b*TT + t] - m) * invZ : 0.f;
}

// context[b,v] = Wv[v,:]·ctxh[b,:] + bv[v].  Warp = one v x 4 batches.
__global__ void k_context(const float* __restrict__ Wv, const float* __restrict__ bv,
                          float* __restrict__ out) {
    int gw   = blockIdx.x * WPB + (threadIdx.x >> 5);
    int lane = threadIdx.x & 31;
    int v  = gw % VDIM;
    int b0 = (gw / VDIM) * 4;
    const float4* w4 = (const float4*)(Wv + (size_t)v * HINDIM);
    float4 w[8];
#pragma unroll
    for (int j = 0; j < 8; j++) w[j] = w4[lane + 32*j];
    float bias = bv[v];
#pragma unroll
    for (int bb = 0; bb < 4; bb++) {
        const float4* c4 = (const float4*)(g_ctxh + (size_t)(b0+bb) * HINDIM);
        float a = 0.f;
#pragma unroll
        for (int j = 0; j < 8; j++) {
            float4 c = c4[lane + 32*j];
            a += w[j].x*c.x + w[j].y*c.y + w[j].z*c.z + w[j].w*c.w;
        }
        a = warp_sum(a);
        if (lane == 0) out[(b0+bb)*VDIM + v] = a + bias;
    }
}

extern "C" void kernel_launch(void* const* d_in, const int* in_sizes, int n_in,
                              void* d_out, int out_size) {
    const float* dec = (const float*)d_in[0];
    const float* lo  = (const float*)d_in[1];
    const int*   len = (const int*)  d_in[2];
    const float* Ws  = (const float*)d_in[3];
    const float* bs  = (const float*)d_in[4];
    const float* Wh  = (const float*)d_in[5];
    const float* bh  = (const float*)d_in[6];  // unused: cancels in softmax
    const float* Wv  = (const float*)d_in[7];
    const float* bv  = (const float*)d_in[8];
    float* out = (float*)d_out;
    (void)bh;

    k_query  <<<KDIM * (BB/4) / WPB, 256>>>(dec, Ws, bs);     // 512 blocks
    k_qhp    <<<dim3(HINDIM/256, KSPLIT), 256>>>(Wh);         // 16 blocks
    k_main   <<<NBLK * BB, 256>>>(lo, len);                   // 512 blocks
    k_bmerge <<<BB, 256>>>(len, out);                         // 32 blocks
    k_context<<<VDIM * (BB/4) / WPB, 256>>>(Wv, bv, out);     // 512 blocks
}